// round 1
// baseline (speedup 1.0000x reference)
#include <cuda_runtime.h>
#include <math.h>

// Problem dims
#define Bc   4
#define NQc  2048
#define NKc  2048
#define Dc   1024
#define Hc   8
#define DKc  128
#define DVc  128
#define DOc  1024

// Scratch (device globals: allocation-free)
__device__ float g_qh[(size_t)Bc * NQc * Hc * DKc];   // (b*NQ+q)*1024 + h*128 + d
__device__ float g_kh[(size_t)Bc * NKc * DKc];        // (b*NK+k)*128 + d
__device__ float g_vh[(size_t)Bc * NKc * DVc];
__device__ float g_outh[(size_t)Bc * NQc * Hc * DVc]; // (b*NQ+q)*1024 + h*128 + d
__device__ float g_rowM[(size_t)Bc * Hc * NQc];
__device__ float g_rowL[(size_t)Bc * Hc * NQc];

// ---------------------------------------------------------------------------
// Generic GEMM: C[M,N] = A[M,K] @ W[N,K]^T + bias[N]
// 64x64 tile, BK=16, 256 threads, 4x4 per thread. All dims divisible by 64/16.
// ---------------------------------------------------------------------------
__global__ void __launch_bounds__(256) gemm_bias_64(
    const float* __restrict__ A, const float* __restrict__ W,
    const float* __restrict__ bias, float* __restrict__ C,
    int M, int N, int K)
{
    __shared__ float As[16 * 68];
    __shared__ float Ws[16 * 68];

    const int tid = threadIdx.x;
    const int tx = tid & 15, ty = tid >> 4;
    const int m0 = blockIdx.y << 6, n0 = blockIdx.x << 6;

    const int lr = tid >> 2;          // 0..63
    const int lc = (tid & 3) << 2;    // 0,4,8,12

    const float* Aptr = A + (size_t)(m0 + lr) * K + lc;
    const float* Wptr = W + (size_t)(n0 + lr) * K + lc;

    float acc[4][4];
#pragma unroll
    for (int i = 0; i < 4; i++)
#pragma unroll
        for (int j = 0; j < 4; j++) acc[i][j] = 0.f;

    for (int k0 = 0; k0 < K; k0 += 16) {
        float4 a = *(const float4*)(Aptr + k0);
        float4 w = *(const float4*)(Wptr + k0);
        As[(lc + 0) * 68 + lr] = a.x;
        As[(lc + 1) * 68 + lr] = a.y;
        As[(lc + 2) * 68 + lr] = a.z;
        As[(lc + 3) * 68 + lr] = a.w;
        Ws[(lc + 0) * 68 + lr] = w.x;
        Ws[(lc + 1) * 68 + lr] = w.y;
        Ws[(lc + 2) * 68 + lr] = w.z;
        Ws[(lc + 3) * 68 + lr] = w.w;
        __syncthreads();
#pragma unroll
        for (int kk = 0; kk < 16; kk++) {
            float4 av = *(const float4*)&As[kk * 68 + (ty << 2)];
            float4 wv = *(const float4*)&Ws[kk * 68 + (tx << 2)];
            float a4[4] = {av.x, av.y, av.z, av.w};
            float w4[4] = {wv.x, wv.y, wv.z, wv.w};
#pragma unroll
            for (int i = 0; i < 4; i++)
#pragma unroll
                for (int j = 0; j < 4; j++) acc[i][j] += a4[i] * w4[j];
        }
        __syncthreads();
    }

    float4 bv = *(const float4*)(bias + n0 + (tx << 2));
#pragma unroll
    for (int i = 0; i < 4; i++) {
        float4 o;
        o.x = acc[i][0] + bv.x;
        o.y = acc[i][1] + bv.y;
        o.z = acc[i][2] + bv.z;
        o.w = acc[i][3] + bv.w;
        *(float4*)(C + (size_t)(m0 + (ty << 2) + i) * N + n0 + (tx << 2)) = o;
    }
}

// ---------------------------------------------------------------------------
// Scores: for (b,h, 64-row q strip) stream all NK in 64-col chunks.
// Writes RAW scores (scaled + mask) into attention output region, tracks
// per-row running max and sum-exp (flash-style).
// Dyn smem: Qs[128][68] + Ks[128][68] = 69,632 B.
// ---------------------------------------------------------------------------
__global__ void __launch_bounds__(256) scores_kernel(
    const float* __restrict__ qh, const float* __restrict__ kh,
    const float* __restrict__ mask, float* __restrict__ attn,
    float* __restrict__ rowM, float* __restrict__ rowL)
{
    extern __shared__ float sm[];
    float* Qs = sm;              // [d][q], 128*68
    float* Ks = sm + 128 * 68;   // [d][k], 128*68

    const int tid = threadIdx.x;
    const int tx = tid & 15, ty = tid >> 4;
    const int q0 = blockIdx.x << 6;
    const int h = blockIdx.y, b = blockIdx.z;
    const float scale = 0.08838834764831845f;  // 1/sqrt(128)

    // Load Q strip once: 64 rows x 128 d
#pragma unroll
    for (int i = 0; i < 8; i++) {
        int idx = tid + i * 256;
        int r = idx >> 5;
        int cg = (idx & 31) << 2;
        float4 v = *(const float4*)(qh + ((size_t)(b * NQc + q0 + r)) * (Hc * DKc)
                                    + h * DKc + cg);
        Qs[(cg + 0) * 68 + r] = v.x;
        Qs[(cg + 1) * 68 + r] = v.y;
        Qs[(cg + 2) * 68 + r] = v.z;
        Qs[(cg + 3) * 68 + r] = v.w;
    }

    float m[4], l[4];
#pragma unroll
    for (int i = 0; i < 4; i++) { m[i] = -1e30f; l[i] = 0.f; }

    for (int ck = 0; ck < NKc / 64; ck++) {
        const int k0 = ck << 6;
#pragma unroll
        for (int i = 0; i < 8; i++) {
            int idx = tid + i * 256;
            int r = idx >> 5;
            int cg = (idx & 31) << 2;
            float4 v = *(const float4*)(kh + ((size_t)(b * NKc + k0 + r)) * DKc + cg);
            Ks[(cg + 0) * 68 + r] = v.x;
            Ks[(cg + 1) * 68 + r] = v.y;
            Ks[(cg + 2) * 68 + r] = v.z;
            Ks[(cg + 3) * 68 + r] = v.w;
        }
        __syncthreads();

        float acc[4][4];
#pragma unroll
        for (int i = 0; i < 4; i++)
#pragma unroll
            for (int j = 0; j < 4; j++) acc[i][j] = 0.f;

#pragma unroll 8
        for (int d = 0; d < 128; d++) {
            float4 qv = *(const float4*)&Qs[d * 68 + (ty << 2)];
            float4 kv = *(const float4*)&Ks[d * 68 + (tx << 2)];
            float a4[4] = {qv.x, qv.y, qv.z, qv.w};
            float w4[4] = {kv.x, kv.y, kv.z, kv.w};
#pragma unroll
            for (int i = 0; i < 4; i++)
#pragma unroll
                for (int j = 0; j < 4; j++) acc[i][j] += a4[i] * w4[j];
        }

#pragma unroll
        for (int i = 0; i < 4; i++) {
            int row = q0 + (ty << 2) + i;
            float4 mv = *(const float4*)(mask + ((size_t)b * NQc + row) * NKc
                                         + k0 + (tx << 2));
            float4 s;
            s.x = acc[i][0] * scale + mv.x;
            s.y = acc[i][1] * scale + mv.y;
            s.z = acc[i][2] * scale + mv.z;
            s.w = acc[i][3] * scale + mv.w;
            *(float4*)(attn + ((size_t)(h * Bc + b) * NQc + row) * NKc
                       + k0 + (tx << 2)) = s;
            float mx = fmaxf(fmaxf(s.x, s.y), fmaxf(s.z, s.w));
            float nm = fmaxf(m[i], mx);
            l[i] = l[i] * __expf(m[i] - nm)
                 + __expf(s.x - nm) + __expf(s.y - nm)
                 + __expf(s.z - nm) + __expf(s.w - nm);
            m[i] = nm;
        }
        __syncthreads();
    }

    // Cross-thread (tx) row reduction; reuse smem
    float* red = sm;   // 64*16 m + 64*16 l = 2048 floats
#pragma unroll
    for (int i = 0; i < 4; i++) {
        int r = (ty << 2) + i;
        red[r * 16 + tx] = m[i];
        red[1024 + r * 16 + tx] = l[i];
    }
    __syncthreads();
    if (tid < 64) {
        int r = tid;
        float M = -1e30f;
#pragma unroll
        for (int j = 0; j < 16; j++) M = fmaxf(M, red[r * 16 + j]);
        float L = 0.f;
#pragma unroll
        for (int j = 0; j < 16; j++)
            L += red[1024 + r * 16 + j] * __expf(red[r * 16 + j] - M);
        int gi = (b * Hc + h) * NQc + q0 + r;
        rowM[gi] = M;
        rowL[gi] = L;
    }
}

// ---------------------------------------------------------------------------
// att@V: re-read raw scores, normalize p = exp(s-M)/L, overwrite attention
// output with p, accumulate outh(64x128) = p @ vh.
// Dyn smem: Ps[64][68] + Vs[64][132] + 128 stats = 51,712 B.
// ---------------------------------------------------------------------------
__global__ void __launch_bounds__(256) attv_kernel(
    const float* __restrict__ vh, float* __restrict__ attn,
    const float* __restrict__ rowM, const float* __restrict__ rowL,
    float* __restrict__ outh)
{
    extern __shared__ float sm[];
    float* Ps = sm;                 // [k][q] 64*68
    float* Vs = sm + 64 * 68;       // [k][d] 64*132
    float* Ms = Vs + 64 * 132;      // 64
    float* Li = Ms + 64;            // 64

    const int tid = threadIdx.x;
    const int tx = tid & 15, ty = tid >> 4;
    const int q0 = blockIdx.x << 6;
    const int h = blockIdx.y, b = blockIdx.z;

    if (tid < 64) {
        int gi = (b * Hc + h) * NQc + q0 + tid;
        Ms[tid] = rowM[gi];
        Li[tid] = 1.0f / rowL[gi];
    }
    __syncthreads();

    float acc[4][8];
#pragma unroll
    for (int i = 0; i < 4; i++)
#pragma unroll
        for (int j = 0; j < 8; j++) acc[i][j] = 0.f;

    for (int ck = 0; ck < NKc / 64; ck++) {
        const int k0 = ck << 6;
        // Load + normalize S tile (64x64), write p back, stage into Ps[k][q]
#pragma unroll
        for (int i = 0; i < 4; i++) {
            int idx = tid + i * 256;
            int r = idx >> 4;
            int cg = (idx & 15) << 2;
            float* ap = attn + ((size_t)(h * Bc + b) * NQc + q0 + r) * NKc + k0 + cg;
            float4 s = *(const float4*)ap;
            float mm = Ms[r], li = Li[r];
            float4 p;
            p.x = __expf(s.x - mm) * li;
            p.y = __expf(s.y - mm) * li;
            p.z = __expf(s.z - mm) * li;
            p.w = __expf(s.w - mm) * li;
            *(float4*)ap = p;
            Ps[(cg + 0) * 68 + r] = p.x;
            Ps[(cg + 1) * 68 + r] = p.y;
            Ps[(cg + 2) * 68 + r] = p.z;
            Ps[(cg + 3) * 68 + r] = p.w;
        }
        // Load V chunk (64 k-rows x 128 d)
#pragma unroll
        for (int i = 0; i < 8; i++) {
            int idx = tid + i * 256;
            int r = idx >> 5;
            int cg = (idx & 31) << 2;
            float4 v = *(const float4*)(vh + ((size_t)(b * NKc + k0 + r)) * DVc + cg);
            *(float4*)&Vs[r * 132 + cg] = v;
        }
        __syncthreads();

#pragma unroll 8
        for (int kk = 0; kk < 64; kk++) {
            float4 pv = *(const float4*)&Ps[kk * 68 + (ty << 2)];
            float4 v0 = *(const float4*)&Vs[kk * 132 + (tx << 3)];
            float4 v1 = *(const float4*)&Vs[kk * 132 + (tx << 3) + 4];
            float p4[4] = {pv.x, pv.y, pv.z, pv.w};
            float v8[8] = {v0.x, v0.y, v0.z, v0.w, v1.x, v1.y, v1.z, v1.w};
#pragma unroll
            for (int i = 0; i < 4; i++)
#pragma unroll
                for (int j = 0; j < 8; j++) acc[i][j] += p4[i] * v8[j];
        }
        __syncthreads();
    }

#pragma unroll
    for (int i = 0; i < 4; i++) {
        int row = q0 + (ty << 2) + i;
        float* op = outh + ((size_t)(b * NQc + row)) * (Hc * DVc) + h * DVc + (tx << 3);
        float4 o0, o1;
        o0.x = acc[i][0]; o0.y = acc[i][1]; o0.z = acc[i][2]; o0.w = acc[i][3];
        o1.x = acc[i][4]; o1.y = acc[i][5]; o1.z = acc[i][6]; o1.w = acc[i][7];
        *(float4*)op = o0;
        *(float4*)(op + 4) = o1;
    }
}

// ---------------------------------------------------------------------------
extern "C" void kernel_launch(void* const* d_in, const int* in_sizes, int n_in,
                              void* d_out, int out_size)
{
    const float* q    = (const float*)d_in[0];
    const float* k    = (const float*)d_in[1];
    const float* v    = (const float*)d_in[2];
    const float* mask = (const float*)d_in[3];
    const float* Wq   = (const float*)d_in[4];
    const float* bq   = (const float*)d_in[5];
    const float* Wk   = (const float*)d_in[6];
    const float* bk   = (const float*)d_in[7];
    const float* Wv   = (const float*)d_in[8];
    const float* bv   = (const float*)d_in[9];
    const float* Wo   = (const float*)d_in[10];
    const float* bo   = (const float*)d_in[11];

    float* attn = (float*)d_out;                              // (H*B, NQ, NK)
    float* outp = attn + (size_t)Hc * Bc * NQc * NKc;         // (B, NQ, DO)

    float *qh, *kh, *vh, *outh, *rm, *rl;
    cudaGetSymbolAddress((void**)&qh,   g_qh);
    cudaGetSymbolAddress((void**)&kh,   g_kh);
    cudaGetSymbolAddress((void**)&vh,   g_vh);
    cudaGetSymbolAddress((void**)&outh, g_outh);
    cudaGetSymbolAddress((void**)&rm,   g_rowM);
    cudaGetSymbolAddress((void**)&rl,   g_rowL);

    dim3 blk(256);
    const int Mrows = Bc * NQc;  // 8192

    // Projections
    gemm_bias_64<<<dim3((Hc * DKc) / 64, Mrows / 64), blk>>>(q, Wq, bq, qh, Mrows, Hc * DKc, Dc);
    gemm_bias_64<<<dim3(DKc / 64, Mrows / 64), blk>>>(k, Wk, bk, kh, Mrows, DKc, Dc);
    gemm_bias_64<<<dim3(DVc / 64, Mrows / 64), blk>>>(v, Wv, bv, vh, Mrows, DVc, Dc);

    // Scores + row stats
    size_t smem2 = (size_t)(2 * 128 * 68) * sizeof(float);   // 69,632 B
    cudaFuncSetAttribute(scores_kernel, cudaFuncAttributeMaxDynamicSharedMemorySize, (int)smem2);
    scores_kernel<<<dim3(NQc / 64, Hc, Bc), blk, smem2>>>(qh, kh, mask, attn, rm, rl);

    // Normalize + att@V
    size_t smem3 = (size_t)(64 * 68 + 64 * 132 + 128) * sizeof(float);  // 51,712 B
    cudaFuncSetAttribute(attv_kernel, cudaFuncAttributeMaxDynamicSharedMemorySize, (int)smem3);
    attv_kernel<<<dim3(NQc / 64, Hc, Bc), blk, smem3>>>(vh, attn, rm, rl, outh);

    // Output projection
    gemm_bias_64<<<dim3(DOc / 64, Mrows / 64), blk>>>(outh, Wo, bo, outp, Mrows, DOc, Hc * DVc);
}